// round 1
// baseline (speedup 1.0000x reference)
#include <cuda_runtime.h>
#include <math.h>
#include <stdint.h>

#define BB 256
#define DD 4096
#define TT 19

// scratch for grad_x = x @ W + b  (4 MB, static device array per harness rules)
__device__ float g_grad[BB * DD];

// ---------------------------------------------------------------------------
// Kernel 1: grad = x @ W + b   (M=256, N=4096, K=4096, fp32)
// Tile 128x64x16, 128 threads, 8x8 micro-tile.
// ---------------------------------------------------------------------------
#define BM 128
#define BN 64
#define BK 16

__global__ void __launch_bounds__(128, 1)
gemm_xw_b(const float* __restrict__ A, const float* __restrict__ Wm,
          const float* __restrict__ bv)
{
    __shared__ float As[BK][BM + 4];
    __shared__ float Bs[BK][BN + 4];
    const int bn = blockIdx.x * BN;
    const int bm = blockIdx.y * BM;
    const int tid = threadIdx.x;
    const int tx = tid & 7;    // 8 col groups
    const int ty = tid >> 3;   // 16 row groups

    float acc[8][8];
#pragma unroll
    for (int i = 0; i < 8; i++)
#pragma unroll
        for (int j = 0; j < 8; j++) acc[i][j] = 0.f;

    for (int k0 = 0; k0 < DD; k0 += BK) {
        // load A tile (x), transpose into As[k][m]
#pragma unroll
        for (int i = 0; i < 4; i++) {
            int f = tid + i * 128;         // 512 float4
            int m = f >> 2, q = f & 3;
            float4 v = *reinterpret_cast<const float4*>(
                A + (size_t)(bm + m) * DD + k0 + q * 4);
            As[q * 4 + 0][m] = v.x;
            As[q * 4 + 1][m] = v.y;
            As[q * 4 + 2][m] = v.z;
            As[q * 4 + 3][m] = v.w;
        }
        // load B tile (W) direct
#pragma unroll
        for (int i = 0; i < 2; i++) {
            int f = tid + i * 128;         // 256 float4
            int k = f >> 4, q = f & 15;
            *reinterpret_cast<float4*>(&Bs[k][q * 4]) =
                *reinterpret_cast<const float4*>(
                    Wm + (size_t)(k0 + k) * DD + bn + q * 4);
        }
        __syncthreads();
#pragma unroll
        for (int kk = 0; kk < BK; kk++) {
            float a[8], b8[8];
            *reinterpret_cast<float4*>(a)      = *reinterpret_cast<float4*>(&As[kk][ty * 8]);
            *reinterpret_cast<float4*>(a + 4)  = *reinterpret_cast<float4*>(&As[kk][ty * 8 + 4]);
            *reinterpret_cast<float4*>(b8)     = *reinterpret_cast<float4*>(&Bs[kk][tx * 8]);
            *reinterpret_cast<float4*>(b8 + 4) = *reinterpret_cast<float4*>(&Bs[kk][tx * 8 + 4]);
#pragma unroll
            for (int i = 0; i < 8; i++)
#pragma unroll
                for (int j = 0; j < 8; j++)
                    acc[i][j] = fmaf(a[i], b8[j], acc[i][j]);
        }
        __syncthreads();
    }

#pragma unroll
    for (int i = 0; i < 8; i++) {
        int m = bm + ty * 8 + i;
#pragma unroll
        for (int j = 0; j < 8; j += 4) {
            int n = bn + tx * 8 + j;
            float4 o;
            o.x = acc[i][j + 0] + bv[n + 0];
            o.y = acc[i][j + 1] + bv[n + 1];
            o.z = acc[i][j + 2] + bv[n + 2];
            o.w = acc[i][j + 3] + bv[n + 3];
            *reinterpret_cast<float4*>(g_grad + (size_t)m * DD + n) = o;
        }
    }
}

// ---------------------------------------------------------------------------
// Kernel 2: per-row sequential Gumbel-max chain + MH accept.
// One block per row (256 blocks, 256 threads).
// ---------------------------------------------------------------------------
#define NT 256
#define PER (DD / NT)   // 16

__global__ void __launch_bounds__(NT, 1)
sampler(const float* __restrict__ x, const float* __restrict__ Wm,
        const float* __restrict__ bv, const float* __restrict__ unif,
        const float* __restrict__ u_accept, const int* __restrict__ radius,
        float* __restrict__ out)
{
    __shared__ float lx[DD];            // 0.5 * grad_x
    __shared__ float ly[DD];            // 0.5 * grad_y
    __shared__ signed char ss[DD];      // current delta sign (1 - 2*cur_x)
    __shared__ signed char s0[DD];      // initial sign (from x)
    __shared__ float rval[NT];
    __shared__ int   ridx[NT];
    __shared__ double rdbl[NT];
    __shared__ int         fidx[TT];    // flipped index per active step
    __shared__ signed char fsb[TT];     // sign BEFORE flip
    __shared__ int   cidx[TT];          // net-changed coords
    __shared__ float cfac[TT];          // 0.5 * net change
    __shared__ int   nchg;
    __shared__ double sh_sx, sh_sy, sh_sf, sh_sb;
    __shared__ int   sh_acc;

    const int r   = blockIdx.x;
    const int tid = threadIdx.x;
    const int rad = radius[r];          // active steps; t >= rad are no-ops

    // ---- init: lx, signs, score_x partial ----
    double part = 0.0;
#pragma unroll
    for (int i = 0; i < PER; i++) {
        int j = i * NT + tid;
        float l = 0.5f * g_grad[(size_t)r * DD + j];
        lx[j] = l;
        float xv = x[(size_t)r * DD + j];
        signed char sgn = (xv > 0.5f) ? (signed char)(-1) : (signed char)1;
        ss[j] = sgn; s0[j] = sgn;
        if (sgn < 0) part += (double)(l + 0.5f * bv[j]);   // score_x = 0.5 x.g + 0.5 x.b
    }
    rdbl[tid] = part; __syncthreads();
    for (int off = NT / 2; off > 0; off >>= 1) {
        if (tid < off) rdbl[tid] += rdbl[tid + off];
        __syncthreads();
    }
    if (tid == 0) sh_sx = rdbl[0];
    __syncthreads();

    // ---- sequential chain: rad Gumbel-argmax steps ----
    for (int t = 0; t < rad; t++) {
        const float* u = unif + ((size_t)t * BB + r) * DD;
        float bvv = -3.4e38f; int bi = 0;
#pragma unroll
        for (int i = 0; i < PER; i++) {
            int j = i * NT + tid;
            float gum = -logf(-logf(u[j]));
            float v = (float)ss[j] * lx[j] + gum;
            if (v > bvv) { bvv = v; bi = j; }        // strict > keeps lowest idx
        }
        rval[tid] = bvv; ridx[tid] = bi;
        __syncthreads();
        for (int off = NT / 2; off > 0; off >>= 1) {
            if (tid < off) {
                float v2 = rval[tid + off]; int i2 = ridx[tid + off];
                if (v2 > rval[tid] || (v2 == rval[tid] && i2 < ridx[tid])) {
                    rval[tid] = v2; ridx[tid] = i2;
                }
            }
            __syncthreads();
        }
        if (tid == 0) {
            int i = ridx[0];
            fidx[t] = i; fsb[t] = ss[i];
            ss[i] = (signed char)(-ss[i]);
        }
        __syncthreads();
    }

    // ---- net-changed coordinates (parity dedupe, serial & deterministic) ----
    if (tid == 0) {
        int n = 0;
        for (int t = 0; t < rad; t++) {
            int i = fidx[t];
            int found = -1;
            for (int k = 0; k < n; k++) if (cidx[k] == i) { found = k; break; }
            if (found >= 0) { cidx[found] = cidx[n - 1]; n--; }
            else cidx[n++] = i;
        }
        nchg = n;
        // net change c = (y - x) at i = -s_final; factor = 0.5*c
        for (int k = 0; k < n; k++) cfac[k] = -0.5f * (float)ss[cidx[k]];
    }
    __syncthreads();

    // ---- ly = lx + sum_k cfac_k * W[row i_k]  (W symmetric: row == column) ----
#pragma unroll
    for (int i = 0; i < PER; i++) {
        int j = i * NT + tid;
        ly[j] = lx[j];
    }
    int nc = nchg;
    for (int k = 0; k < nc; k++) {
        const float* wr = Wm + (size_t)cidx[k] * DD;
        float f = cfac[k];
#pragma unroll
        for (int i = 0; i < PER; i++) {
            int j = i * NT + tid;
            ly[j] = fmaf(f, wr[j], ly[j]);
        }
    }

    // ---- score_y, base lse sums (double accumulate) ----
    double psy = 0.0, psf = 0.0, psb = 0.0;
#pragma unroll
    for (int i = 0; i < PER; i++) {
        int j = i * NT + tid;
        float lyj = ly[j], lxj = lx[j];
        if (ss[j] < 0) psy += (double)(lyj + 0.5f * bv[j]);   // y_j = 1 where sign<0
        psf += (double)expf((float)s0[j] * lxj);              // lse base, state D_0, grad_x
        psb += (double)expf((float)ss[j] * lyj);              // lse base, final state, grad_y
    }
    rdbl[tid] = psy; __syncthreads();
    for (int off = NT / 2; off > 0; off >>= 1) { if (tid < off) rdbl[tid] += rdbl[tid + off]; __syncthreads(); }
    if (tid == 0) sh_sy = rdbl[0];
    __syncthreads();
    rdbl[tid] = psf; __syncthreads();
    for (int off = NT / 2; off > 0; off >>= 1) { if (tid < off) rdbl[tid] += rdbl[tid + off]; __syncthreads(); }
    if (tid == 0) sh_sf = rdbl[0];
    __syncthreads();
    rdbl[tid] = psb; __syncthreads();
    for (int off = NT / 2; off > 0; off >>= 1) { if (tid < off) rdbl[tid] += rdbl[tid + off]; __syncthreads(); }
    if (tid == 0) sh_sb = rdbl[0];
    __syncthreads();

    // ---- serial accept math: incremental lse walks (O(1) per flip) ----
    if (tid == 0) {
        // forward: states D_0 .. D_{rad-1}, logits = sign * lx
        double S = sh_sf, lf = 0.0;
        for (int t = 0; t < rad; t++) {
            int i = fidx[t]; float sb = (float)fsb[t]; float l = lx[i];
            lf += (double)(sb * l) - log(S);
            S += exp((double)(-sb * l)) - exp((double)(sb * l));   // apply flip
        }
        lf += sh_sx;

        // backward: states D_rad (final) down to D_1, logits = sign * ly,
        // term t selects idx_t with sign AFTER flip t (= -fsb[t])
        double Sb = sh_sb, lb = 0.0;
        for (int t = rad - 1; t >= 0; t--) {
            int i = fidx[t]; float sb = (float)fsb[t]; float l = ly[i];
            lb += (double)(-sb * l) - log(Sb);
            Sb += exp((double)(sb * l)) - exp((double)(-sb * l));  // undo flip
        }
        lb += sh_sy;

        float ratio = expf((float)(lb - lf));
        sh_acc = (ratio >= u_accept[r]) ? 1 : 0;
    }
    __syncthreads();

    // ---- write output: y if accepted else x ----
    int acc = sh_acc;
#pragma unroll
    for (int i = 0; i < PER; i++) {
        int j = i * NT + tid;
        float yv = (ss[j] < 0) ? 1.f : 0.f;
        float xv = (s0[j] < 0) ? 1.f : 0.f;
        out[(size_t)r * DD + j] = acc ? yv : xv;
    }
}

// ---------------------------------------------------------------------------
extern "C" void kernel_launch(void* const* d_in, const int* in_sizes, int n_in,
                              void* d_out, int out_size)
{
    (void)in_sizes; (void)n_in; (void)out_size;
    const float* x    = (const float*)d_in[0];
    const float* Wm   = (const float*)d_in[1];
    const float* bv   = (const float*)d_in[2];
    const float* unif = (const float*)d_in[3];
    const float* ua   = (const float*)d_in[4];
    const int*   rad  = (const int*)d_in[5];
    float* out = (float*)d_out;

    dim3 ggrid(DD / BN, BB / BM);   // (64, 2)
    gemm_xw_b<<<ggrid, 128>>>(x, Wm, bv);
    sampler<<<BB, NT>>>(x, Wm, bv, unif, ua, rad, out);
}

// round 3
// speedup vs baseline: 2.8783x; 2.8783x over previous
#include <cuda_runtime.h>
#include <math.h>
#include <stdint.h>

#define BB 256
#define DD 4096
#define TT 19

// ---------------- static device scratch ------------------------------------
__device__ float g_grad[BB * DD];                     // 4 MB  grad_x = xW + b
__device__ signed char g_As8[BB * DD];                // 1 MB  x as s8
__device__ signed char g_Bq[3][(size_t)DD * DD];      // 48 MB W digit planes
__device__ int g_acc[3][BB * DD];                     // 12 MB s32 partial sums

// ---------------------------------------------------------------------------
// conv_w: W fp32 -> 3 balanced s8 digit planes of rint(W * 2^26).
// Layout identical to W ([n][k]); W symmetric so no transpose needed.
// ---------------------------------------------------------------------------
union B8 { signed char c[8]; uint2 u; };

__global__ void __launch_bounds__(256) conv_w(const float* __restrict__ W)
{
    size_t e = ((size_t)blockIdx.x * 256 + threadIdx.x) * 8;
    float4 a = *reinterpret_cast<const float4*>(W + e);
    float4 b = *reinterpret_cast<const float4*>(W + e + 4);
    float w[8] = {a.x, a.y, a.z, a.w, b.x, b.y, b.z, b.w};
    B8 p0, p1, p2;
#pragma unroll
    for (int i = 0; i < 8; i++) {
        int v = __float2int_rn(w[i] * 67108864.0f);   // exact: *2^26 then rint
        v = max(-8000000, min(8000000, v));           // safety clamp (never hit)
        int d0 = ((v + 128) & 255) - 128; v = (v - d0) >> 8;
        int d1 = ((v + 128) & 255) - 128; v = (v - d1) >> 8;
        p0.c[i] = (signed char)d0;
        p1.c[i] = (signed char)d1;
        p2.c[i] = (signed char)v;
    }
    *reinterpret_cast<uint2*>(&g_Bq[0][e]) = p0.u;
    *reinterpret_cast<uint2*>(&g_Bq[1][e]) = p1.u;
    *reinterpret_cast<uint2*>(&g_Bq[2][e]) = p2.u;
}

__global__ void __launch_bounds__(256) conv_a(const float* __restrict__ x)
{
    size_t e = ((size_t)blockIdx.x * 256 + threadIdx.x) * 8;
    float4 a = *reinterpret_cast<const float4*>(x + e);
    float4 b = *reinterpret_cast<const float4*>(x + e + 4);
    float w[8] = {a.x, a.y, a.z, a.w, b.x, b.y, b.z, b.w};
    B8 p;
#pragma unroll
    for (int i = 0; i < 8; i++) p.c[i] = (signed char)(w[i] > 0.5f ? 1 : 0);
    *reinterpret_cast<uint2*>(&g_As8[e]) = p.u;
}

// ---------------------------------------------------------------------------
// int8 tensor-core GEMM: acc[plane] = x_s8 @ plane^T  (s32, exact).
// CTA tile 128M x 64N x K4096, BK=64 bytes, 4-stage cp.async pipeline.
// 8 warps = 4M x 2N, warp tile 32x32, mma m16n8k32.
// ---------------------------------------------------------------------------
#define AST 10240           // A stage: 128 rows * 80B
#define BST 5120            // B stage:  64 rows * 80B
#define STB (AST + BST)     // 15360
#define GSMEM (4 * STB)     // 61440

__device__ __forceinline__ uint32_t smem_u32(const void* p) {
    uint32_t a;
    asm("{ .reg .u64 t; cvta.to.shared.u64 t, %1; cvt.u32.u64 %0, t; }" : "=r"(a) : "l"(p));
    return a;
}

__device__ __forceinline__ void cpa16(uint32_t dst, const void* src) {
    asm volatile("cp.async.cg.shared.global [%0], [%1], 16;" :: "r"(dst), "l"(src));
}
__device__ __forceinline__ void ldm4(uint32_t& r0, uint32_t& r1, uint32_t& r2, uint32_t& r3,
                                     uint32_t addr) {
    asm volatile("ldmatrix.sync.aligned.m8n8.x4.shared.b16 {%0,%1,%2,%3}, [%4];"
                 : "=r"(r0), "=r"(r1), "=r"(r2), "=r"(r3) : "r"(addr));
}
__device__ __forceinline__ void mma_s8(int* d, const uint32_t* aa, const uint32_t* bb) {
    asm volatile("mma.sync.aligned.m16n8k32.row.col.s32.s8.s8.s32 "
                 "{%0,%1,%2,%3}, {%4,%5,%6,%7}, {%8,%9}, {%0,%1,%2,%3};"
                 : "+r"(d[0]), "+r"(d[1]), "+r"(d[2]), "+r"(d[3])
                 : "r"(aa[0]), "r"(aa[1]), "r"(aa[2]), "r"(aa[3]), "r"(bb[0]), "r"(bb[1]));
}

__global__ void __launch_bounds__(256, 2) gemm_i8()
{
    extern __shared__ __align__(128) char dsm[];
    const uint32_t sbase = smem_u32(dsm);

    const int tid = threadIdx.x;
    const int wid = tid >> 5;
    const int lane = tid & 31;
    const int nt = blockIdx.x;         // 0..63
    const int mt = blockIdx.y;         // 0..1
    const int plane = blockIdx.z;      // 0..2
    const int wm = wid & 3;            // warp M group
    const int wn = wid >> 2;           // warp N group
    const int gp = lane >> 2;          // groupid
    const int t4 = lane & 3;

    const signed char* Bp = g_Bq[plane];

    // per-thread load slots: 3 x 16B chunks per stage
    const int cA0 = tid;               // A chunks 0..511
    const int cA1 = tid + 256;
    const int cB  = tid;               // B chunks 0..255

    int acc[2][4][4];
#pragma unroll
    for (int i = 0; i < 2; i++)
#pragma unroll
        for (int j = 0; j < 4; j++)
#pragma unroll
            for (int q = 0; q < 4; q++) acc[i][j][q] = 0;

    auto load_stage = [&](int s, int it) {
        const int k0 = it * 64;
        uint32_t sb = sbase + s * STB;
        {
            int row = cA0 >> 2, col = cA0 & 3;
            cpa16(sb + row * 80 + col * 16,
                  g_As8 + (size_t)(mt * 128 + row) * DD + k0 + col * 16);
        }
        {
            int row = cA1 >> 2, col = cA1 & 3;
            cpa16(sb + row * 80 + col * 16,
                  g_As8 + (size_t)(mt * 128 + row) * DD + k0 + col * 16);
        }
        {
            int row = cB >> 2, col = cB & 3;
            cpa16(sb + AST + row * 80 + col * 16,
                  Bp + (size_t)(nt * 64 + row) * DD + k0 + col * 16);
        }
    };

    // prologue: 3 stages in flight
#pragma unroll
    for (int p = 0; p < 3; p++) {
        load_stage(p, p);
        asm volatile("cp.async.commit_group;");
    }

    // precomputed lane address components
    const int a_tile = lane >> 3, a_r = lane & 7;
    const int arow_base = wm * 32 + ((a_tile & 1) ? 8 : 0) + a_r;   // + mi*16
    const int abyte_base = (a_tile >> 1) ? 16 : 0;                  // + ks*32
    const int brow_base = wn * 32 + ((a_tile >> 1) ? 8 : 0) + a_r;  // + j*8
    const int bbyte_base = (a_tile & 1) ? 16 : 0;                   // + ks*32

    for (int i = 0; i < 64; i++) {
        asm volatile("cp.async.wait_group 2;");
        __syncthreads();
        if (i + 3 < 64) load_stage((i + 3) & 3, i + 3);
        asm volatile("cp.async.commit_group;");

        const uint32_t sb = sbase + (i & 3) * STB;
#pragma unroll
        for (int ks = 0; ks < 2; ks++) {
            uint32_t afr[2][4];
#pragma unroll
            for (int mi = 0; mi < 2; mi++) {
                uint32_t addr = sb + (arow_base + mi * 16) * 80 + abyte_base + ks * 32;
                ldm4(afr[mi][0], afr[mi][1], afr[mi][2], afr[mi][3], addr);
            }
            uint32_t bfr[4][2];
#pragma unroll
            for (int jj = 0; jj < 4; jj += 2) {
                uint32_t addr = sb + AST + (brow_base + jj * 8) * 80 + bbyte_base + ks * 32;
                uint32_t r0, r1, r2, r3;
                ldm4(r0, r1, r2, r3, addr);
                bfr[jj][0] = r0; bfr[jj][1] = r1;
                bfr[jj + 1][0] = r2; bfr[jj + 1][1] = r3;
            }
#pragma unroll
            for (int mi = 0; mi < 2; mi++)
#pragma unroll
                for (int nj = 0; nj < 4; nj++)
                    mma_s8(acc[mi][nj], afr[mi], bfr[nj]);
        }
        __syncthreads();
    }

    // epilogue: write s32 accumulators
    int* accp = g_acc[plane];
#pragma unroll
    for (int mi = 0; mi < 2; mi++)
#pragma unroll
        for (int nj = 0; nj < 4; nj++) {
            int row0 = mt * 128 + wm * 32 + mi * 16 + gp;
            int col  = nt * 64 + wn * 32 + nj * 8 + t4 * 2;
            int2 v0 = make_int2(acc[mi][nj][0], acc[mi][nj][1]);
            int2 v1 = make_int2(acc[mi][nj][2], acc[mi][nj][3]);
            *reinterpret_cast<int2*>(accp + (size_t)row0 * DD + col) = v0;
            *reinterpret_cast<int2*>(accp + (size_t)(row0 + 8) * DD + col) = v1;
        }
}

// ---------------------------------------------------------------------------
// combine: grad = (acc2*2^16 + acc1*2^8 + acc0) * 2^-26 + b
// ---------------------------------------------------------------------------
__global__ void __launch_bounds__(256) combine(const float* __restrict__ bv)
{
    size_t e = ((size_t)blockIdx.x * 256 + threadIdx.x) * 4;
    int4 a0 = *reinterpret_cast<const int4*>(&g_acc[0][e]);
    int4 a1 = *reinterpret_cast<const int4*>(&g_acc[1][e]);
    int4 a2 = *reinterpret_cast<const int4*>(&g_acc[2][e]);
    int n = (int)(e & (DD - 1));
    float4 bb = *reinterpret_cast<const float4*>(bv + n);
    const double s = 1.0 / 67108864.0;
    float4 o;
    o.x = (float)(((double)((long long)a0.x + ((long long)a1.x << 8) + ((long long)a2.x << 16))) * s + (double)bb.x);
    o.y = (float)(((double)((long long)a0.y + ((long long)a1.y << 8) + ((long long)a2.y << 16))) * s + (double)bb.y);
    o.z = (float)(((double)((long long)a0.z + ((long long)a1.z << 8) + ((long long)a2.z << 16))) * s + (double)bb.z);
    o.w = (float)(((double)((long long)a0.w + ((long long)a1.w << 8) + ((long long)a2.w << 16))) * s + (double)bb.w);
    *reinterpret_cast<float4*>(g_grad + e) = o;
}

// ---------------------------------------------------------------------------
// Sampler: per-row Gumbel-max chain with pruned log evaluation + MH accept.
// ---------------------------------------------------------------------------
#define NT 256
#define PER (DD / NT)

__global__ void __launch_bounds__(NT, 1)
sampler(const float* __restrict__ x, const float* __restrict__ Wm,
        const float* __restrict__ bv, const float* __restrict__ unif,
        const float* __restrict__ u_accept, const int* __restrict__ radius,
        float* __restrict__ out)
{
    __shared__ float lx[DD];
    __shared__ float ly[DD];
    __shared__ signed char ss[DD];
    __shared__ signed char s0[DD];
    __shared__ float rval[8];
    __shared__ int   ridx[8];
    __shared__ double rdbl[NT];
    __shared__ int         fidx[TT];
    __shared__ signed char fsb[TT];
    __shared__ int   cidx[TT];
    __shared__ float cfac[TT];
    __shared__ int   nchg;
    __shared__ float sh_L;
    __shared__ double sh_sx, sh_sy, sh_sf, sh_sb;
    __shared__ int   sh_acc;

    const int r   = blockIdx.x;
    const int tid = threadIdx.x;
    const int rad = radius[r];

    // ---- init: lx, signs, score_x, Lmax ----
    double part = 0.0;
    float lmax = 0.f;
#pragma unroll
    for (int i = 0; i < PER; i++) {
        int j = i * NT + tid;
        float l = 0.5f * g_grad[(size_t)r * DD + j];
        lx[j] = l;
        lmax = fmaxf(lmax, fabsf(l));
        float xv = x[(size_t)r * DD + j];
        signed char sgn = (xv > 0.5f) ? (signed char)(-1) : (signed char)1;
        ss[j] = sgn; s0[j] = sgn;
        if (sgn < 0) part += (double)(l + 0.5f * bv[j]);
    }
#pragma unroll
    for (int off = 16; off > 0; off >>= 1)
        lmax = fmaxf(lmax, __shfl_down_sync(0xffffffffu, lmax, off));
    if ((tid & 31) == 0) rval[tid >> 5] = lmax;
    rdbl[tid] = part; __syncthreads();
    if (tid == 0) {
        float m = rval[0];
        for (int w = 1; w < 8; w++) m = fmaxf(m, rval[w]);
        sh_L = m;
    }
    for (int off = NT / 2; off > 0; off >>= 1) {
        if (tid < off) rdbl[tid] += rdbl[tid + off];
        __syncthreads();
    }
    if (tid == 0) sh_sx = rdbl[0];
    __syncthreads();
    const float Lmax = sh_L;

    // ---- sequential chain ----
    for (int t = 0; t < rad; t++) {
        const float4* up = reinterpret_cast<const float4*>(unif + ((size_t)t * BB + r) * DD);
        float uv[16];
        float um = -1.f; int im = 0;
#pragma unroll
        for (int c = 0; c < 4; c++) {
            float4 U = up[c * 256 + tid];
            int j = c * 1024 + tid * 4;
            uv[c * 4 + 0] = U.x; uv[c * 4 + 1] = U.y;
            uv[c * 4 + 2] = U.z; uv[c * 4 + 3] = U.w;
            if (U.x > um) { um = U.x; im = j; }
            if (U.y > um) { um = U.y; im = j + 1; }
            if (U.z > um) { um = U.z; im = j + 2; }
            if (U.w > um) { um = U.w; im = j + 3; }
        }
        // block argmax of u
#pragma unroll
        for (int off = 16; off > 0; off >>= 1) {
            float v2 = __shfl_down_sync(0xffffffffu, um, off);
            int i2 = __shfl_down_sync(0xffffffffu, im, off);
            if (v2 > um || (v2 == um && i2 < im)) { um = v2; im = i2; }
        }
        if ((tid & 31) == 0) { rval[tid >> 5] = um; ridx[tid >> 5] = im; }
        __syncthreads();
        if (tid < 8) {
            float v = rval[tid]; int i = ridx[tid];
#pragma unroll
            for (int off = 4; off > 0; off >>= 1) {
                float v2 = __shfl_down_sync(0xffu, v, off);
                int i2 = __shfl_down_sync(0xffu, i, off);
                if (v2 > v || (v2 == v && i2 < i)) { v = v2; i = i2; }
            }
            if (tid == 0) { rval[0] = v; ridx[0] = i; }
        }
        __syncthreads();
        const float umax = rval[0];
        const int imax = ridx[0];
        const float slm = (float)ss[imax] * lx[imax];
        const float gm = -logf(-logf(umax));
        const float thr_g = gm + slm - Lmax - 0.05f;
        const float uth = expf(-expf(-thr_g));

        // pruned pass: logf only for candidates
        float bvv = -3.4e38f; int bi = 0;
#pragma unroll
        for (int i = 0; i < 16; i++) {
            if (uv[i] >= uth) {
                int j = (i >> 2) * 1024 + tid * 4 + (i & 3);
                float g = -logf(-logf(uv[i]));
                float v = (float)ss[j] * lx[j] + g;
                if (v > bvv) { bvv = v; bi = j; }
            }
        }
#pragma unroll
        for (int off = 16; off > 0; off >>= 1) {
            float v2 = __shfl_down_sync(0xffffffffu, bvv, off);
            int i2 = __shfl_down_sync(0xffffffffu, bi, off);
            if (v2 > bvv || (v2 == bvv && i2 < bi)) { bvv = v2; bi = i2; }
        }
        if ((tid & 31) == 0) { rval[tid >> 5] = bvv; ridx[tid >> 5] = bi; }
        __syncthreads();
        if (tid < 8) {
            float v = rval[tid]; int i = ridx[tid];
#pragma unroll
            for (int off = 4; off > 0; off >>= 1) {
                float v2 = __shfl_down_sync(0xffu, v, off);
                int i2 = __shfl_down_sync(0xffu, i, off);
                if (v2 > v || (v2 == v && i2 < i)) { v = v2; i = i2; }
            }
            if (tid == 0) { fidx[t] = i; fsb[t] = ss[i]; ss[i] = (signed char)(-ss[i]); }
        }
        __syncthreads();
    }

    // ---- net-changed coordinates ----
    if (tid == 0) {
        int n = 0;
        for (int t = 0; t < rad; t++) {
            int i = fidx[t];
            int found = -1;
            for (int k = 0; k < n; k++) if (cidx[k] == i) { found = k; break; }
            if (found >= 0) { cidx[found] = cidx[n - 1]; n--; }
            else cidx[n++] = i;
        }
        nchg = n;
        for (int k = 0; k < n; k++) cfac[k] = -0.5f * (float)ss[cidx[k]];
    }
    __syncthreads();

    // ---- ly = lx + sum cfac_k * W[i_k] (W symmetric) ----
#pragma unroll
    for (int i = 0; i < PER; i++) {
        int j = i * NT + tid;
        ly[j] = lx[j];
    }
    int nc = nchg;
    for (int k = 0; k < nc; k++) {
        const float* wr = Wm + (size_t)cidx[k] * DD;
        float f = cfac[k];
#pragma unroll
        for (int i = 0; i < PER; i++) {
            int j = i * NT + tid;
            ly[j] = fmaf(f, wr[j], ly[j]);
        }
    }

    // ---- score_y + base lse sums ----
    double psy = 0.0, psf = 0.0, psb = 0.0;
#pragma unroll
    for (int i = 0; i < PER; i++) {
        int j = i * NT + tid;
        float lyj = ly[j], lxj = lx[j];
        if (ss[j] < 0) psy += (double)(lyj + 0.5f * bv[j]);
        psf += (double)expf((float)s0[j] * lxj);
        psb += (double)expf((float)ss[j] * lyj);
    }
    rdbl[tid] = psy; __syncthreads();
    for (int off = NT / 2; off > 0; off >>= 1) { if (tid < off) rdbl[tid] += rdbl[tid + off]; __syncthreads(); }
    if (tid == 0) sh_sy = rdbl[0];
    __syncthreads();
    rdbl[tid] = psf; __syncthreads();
    for (int off = NT / 2; off > 0; off >>= 1) { if (tid < off) rdbl[tid] += rdbl[tid + off]; __syncthreads(); }
    if (tid == 0) sh_sf = rdbl[0];
    __syncthreads();
    rdbl[tid] = psb; __syncthreads();
    for (int off = NT / 2; off > 0; off >>= 1) { if (tid < off) rdbl[tid] += rdbl[tid + off]; __syncthreads(); }
    if (tid == 0) sh_sb = rdbl[0];
    __syncthreads();

    // ---- serial accept math (incremental lse walks) ----
    if (tid == 0) {
        double S = sh_sf, lf = 0.0;
        for (int t = 0; t < rad; t++) {
            int i = fidx[t]; float sb = (float)fsb[t]; float l = lx[i];
            lf += (double)(sb * l) - log(S);
            S += exp((double)(-sb * l)) - exp((double)(sb * l));
        }
        lf += sh_sx;

        double Sb = sh_sb, lb = 0.0;
        for (int t = rad - 1; t >= 0; t--) {
            int i = fidx[t]; float sb = (float)fsb[t]; float l = ly[i];
            lb += (double)(-sb * l) - log(Sb);
            Sb += exp((double)(sb * l)) - exp((double)(-sb * l));
        }
        lb += sh_sy;

        float ratio = expf((float)(lb - lf));
        sh_acc = (ratio >= u_accept[r]) ? 1 : 0;
    }
    __syncthreads();

    int acc = sh_acc;
#pragma unroll
    for (int i = 0; i < PER; i++) {
        int j = i * NT + tid;
        float yv = (ss[j] < 0) ? 1.f : 0.f;
        float xv = (s0[j] < 0) ? 1.f : 0.f;
        out[(size_t)r * DD + j] = acc ? yv : xv;
    }
}

// ---------------------------------------------------------------------------
extern "C" void kernel_launch(void* const* d_in, const int* in_sizes, int n_in,
                              void* d_out, int out_size)
{
    (void)in_sizes; (void)n_in; (void)out_size;
    const float* x    = (const float*)d_in[0];
    const float* Wm   = (const float*)d_in[1];
    const float* bv   = (const float*)d_in[2];
    const float* unif = (const float*)d_in[3];
    const float* ua   = (const float*)d_in[4];
    const int*   rad  = (const int*)d_in[5];
    float* out = (float*)d_out;

    static int attr_done = 0;
    if (!attr_done) {
        cudaFuncSetAttribute(gemm_i8, cudaFuncAttributeMaxDynamicSharedMemorySize, GSMEM);
        attr_done = 1;
    }

    conv_w<<<8192, 256>>>(Wm);
    conv_a<<<512, 256>>>(x);
    gemm_i8<<<dim3(64, 2, 3), 256, GSMEM>>>();
    combine<<<1024, 256>>>(bv);
    sampler<<<BB, NT>>>(x, Wm, bv, unif, ua, rad, out);
}

// round 4
// speedup vs baseline: 2.9086x; 1.0105x over previous
#include <cuda_runtime.h>
#include <math.h>
#include <stdint.h>

#define BB 256
#define DD 4096
#define TT 19

// ---------------- static device scratch ------------------------------------
__device__ float g_grad[BB * DD];                     // 4 MB  grad_x = xW + b
__device__ signed char g_As8[BB * DD];                // 1 MB  x as s8
__device__ signed char g_Bq[3][(size_t)DD * DD];      // 48 MB W digit planes

// ---------------------------------------------------------------------------
// conv_w: W fp32 -> 3 balanced s8 digit planes of rint(W * 2^26).
// ---------------------------------------------------------------------------
union B8 { signed char c[8]; uint2 u; };

__global__ void __launch_bounds__(256) conv_w(const float* __restrict__ W)
{
    size_t e = ((size_t)blockIdx.x * 256 + threadIdx.x) * 8;
    float4 a = *reinterpret_cast<const float4*>(W + e);
    float4 b = *reinterpret_cast<const float4*>(W + e + 4);
    float w[8] = {a.x, a.y, a.z, a.w, b.x, b.y, b.z, b.w};
    B8 p0, p1, p2;
#pragma unroll
    for (int i = 0; i < 8; i++) {
        int v = __float2int_rn(w[i] * 67108864.0f);
        v = max(-8000000, min(8000000, v));
        int d0 = ((v + 128) & 255) - 128; v = (v - d0) >> 8;
        int d1 = ((v + 128) & 255) - 128; v = (v - d1) >> 8;
        p0.c[i] = (signed char)d0;
        p1.c[i] = (signed char)d1;
        p2.c[i] = (signed char)v;
    }
    *reinterpret_cast<uint2*>(&g_Bq[0][e]) = p0.u;
    *reinterpret_cast<uint2*>(&g_Bq[1][e]) = p1.u;
    *reinterpret_cast<uint2*>(&g_Bq[2][e]) = p2.u;
}

__global__ void __launch_bounds__(256) conv_a(const float* __restrict__ x)
{
    size_t e = ((size_t)blockIdx.x * 256 + threadIdx.x) * 8;
    float4 a = *reinterpret_cast<const float4*>(x + e);
    float4 b = *reinterpret_cast<const float4*>(x + e + 4);
    float w[8] = {a.x, a.y, a.z, a.w, b.x, b.y, b.z, b.w};
    B8 p;
#pragma unroll
    for (int i = 0; i < 8; i++) p.c[i] = (signed char)(w[i] > 0.5f ? 1 : 0);
    *reinterpret_cast<uint2*>(&g_As8[e]) = p.u;
}

// ---------------------------------------------------------------------------
// Fused int8 tensor-core GEMM over all 3 digit planes (K=12288), radix-256
// accumulator scaling at plane boundaries. Epilogue writes fp32 grad + b.
// CTA tile 128M x 64N, BK=64B, 4-stage cp.async pipeline, 8 warps 32x32.
// ---------------------------------------------------------------------------
#define AST 10240
#define BST 5120
#define STB (AST + BST)
#define GSMEM (4 * STB)
#define KITERS 192          // 3 planes * 64 chunks

__device__ __forceinline__ uint32_t smem_u32(const void* p) {
    uint32_t a;
    asm("{ .reg .u64 t; cvta.to.shared.u64 t, %1; cvt.u32.u64 %0, t; }" : "=r"(a) : "l"(p));
    return a;
}
__device__ __forceinline__ void cpa16(uint32_t dst, const void* src) {
    asm volatile("cp.async.cg.shared.global [%0], [%1], 16;" :: "r"(dst), "l"(src));
}
__device__ __forceinline__ void ldm4(uint32_t& r0, uint32_t& r1, uint32_t& r2, uint32_t& r3,
                                     uint32_t addr) {
    asm volatile("ldmatrix.sync.aligned.m8n8.x4.shared.b16 {%0,%1,%2,%3}, [%4];"
                 : "=r"(r0), "=r"(r1), "=r"(r2), "=r"(r3) : "r"(addr));
}
__device__ __forceinline__ void mma_s8(int* d, const uint32_t* aa, const uint32_t* bb) {
    asm volatile("mma.sync.aligned.m16n8k32.row.col.s32.s8.s8.s32 "
                 "{%0,%1,%2,%3}, {%4,%5,%6,%7}, {%8,%9}, {%0,%1,%2,%3};"
                 : "+r"(d[0]), "+r"(d[1]), "+r"(d[2]), "+r"(d[3])
                 : "r"(aa[0]), "r"(aa[1]), "r"(aa[2]), "r"(aa[3]), "r"(bb[0]), "r"(bb[1]));
}

__global__ void __launch_bounds__(256, 2) gemm_i8(const float* __restrict__ bv)
{
    extern __shared__ __align__(128) char dsm[];
    const uint32_t sbase = smem_u32(dsm);

    const int tid = threadIdx.x;
    const int wid = tid >> 5;
    const int lane = tid & 31;
    const int nt = blockIdx.x;         // 0..63
    const int mt = blockIdx.y;         // 0..1
    const int wm = wid & 3;
    const int wn = wid >> 2;
    const int gp = lane >> 2;
    const int t4 = lane & 3;

    const int cA0 = tid, cA1 = tid + 256, cB = tid;

    int acc[2][4][4];
#pragma unroll
    for (int i = 0; i < 2; i++)
#pragma unroll
        for (int j = 0; j < 4; j++)
#pragma unroll
            for (int q = 0; q < 4; q++) acc[i][j][q] = 0;

    auto load_stage = [&](int s, int it) {
        const int plane = 2 - (it >> 6);       // d2 first, then d1, d0
        const int k0 = (it & 63) * 64;
        const signed char* Bp = g_Bq[0] + (size_t)plane * ((size_t)DD * DD);
        uint32_t sb = sbase + s * STB;
        {
            int row = cA0 >> 2, col = cA0 & 3;
            cpa16(sb + row * 80 + col * 16,
                  g_As8 + (size_t)(mt * 128 + row) * DD + k0 + col * 16);
        }
        {
            int row = cA1 >> 2, col = cA1 & 3;
            cpa16(sb + row * 80 + col * 16,
                  g_As8 + (size_t)(mt * 128 + row) * DD + k0 + col * 16);
        }
        {
            int row = cB >> 2, col = cB & 3;
            cpa16(sb + AST + row * 80 + col * 16,
                  Bp + (size_t)(nt * 64 + row) * DD + k0 + col * 16);
        }
    };

#pragma unroll
    for (int p = 0; p < 3; p++) {
        load_stage(p, p);
        asm volatile("cp.async.commit_group;");
    }

    const int a_tile = lane >> 3, a_r = lane & 7;
    const int arow_base = wm * 32 + ((a_tile & 1) ? 8 : 0) + a_r;
    const int abyte_base = (a_tile >> 1) ? 16 : 0;
    const int brow_base = wn * 32 + ((a_tile >> 1) ? 8 : 0) + a_r;
    const int bbyte_base = (a_tile & 1) ? 16 : 0;

    for (int i = 0; i < KITERS; i++) {
        asm volatile("cp.async.wait_group 2;");
        __syncthreads();
        if (i + 3 < KITERS) load_stage((i + 3) & 3, i + 3);
        asm volatile("cp.async.commit_group;");

        const uint32_t sb = sbase + (i & 3) * STB;
#pragma unroll
        for (int ks = 0; ks < 2; ks++) {
            uint32_t afr[2][4];
#pragma unroll
            for (int mi = 0; mi < 2; mi++) {
                uint32_t addr = sb + (arow_base + mi * 16) * 80 + abyte_base + ks * 32;
                ldm4(afr[mi][0], afr[mi][1], afr[mi][2], afr[mi][3], addr);
            }
            uint32_t bfr[4][2];
#pragma unroll
            for (int jj = 0; jj < 4; jj += 2) {
                uint32_t addr = sb + AST + (brow_base + jj * 8) * 80 + bbyte_base + ks * 32;
                uint32_t r0, r1, r2, r3;
                ldm4(r0, r1, r2, r3, addr);
                bfr[jj][0] = r0; bfr[jj][1] = r1;
                bfr[jj + 1][0] = r2; bfr[jj + 1][1] = r3;
            }
#pragma unroll
            for (int mi = 0; mi < 2; mi++)
#pragma unroll
                for (int nj = 0; nj < 4; nj++)
                    mma_s8(acc[mi][nj], afr[mi], bfr[nj]);
        }
        __syncthreads();

        // radix scaling at plane boundaries (exact: values stay << 2^31)
        if (i == 63 || i == 127) {
#pragma unroll
            for (int mi = 0; mi < 2; mi++)
#pragma unroll
                for (int nj = 0; nj < 4; nj++)
#pragma unroll
                    for (int q = 0; q < 4; q++) acc[mi][nj][q] <<= 8;
        }
    }

    // epilogue: grad = acc * 2^-26 + b  (double combine matches prior exactness)
    const double s = 1.0 / 67108864.0;
#pragma unroll
    for (int mi = 0; mi < 2; mi++)
#pragma unroll
        for (int nj = 0; nj < 4; nj++) {
            int row0 = mt * 128 + wm * 32 + mi * 16 + gp;
            int col  = nt * 64 + wn * 32 + nj * 8 + t4 * 2;
            float b0 = bv[col], b1 = bv[col + 1];
            float2 v0, v1;
            v0.x = (float)((double)acc[mi][nj][0] * s + (double)b0);
            v0.y = (float)((double)acc[mi][nj][1] * s + (double)b1);
            v1.x = (float)((double)acc[mi][nj][2] * s + (double)b0);
            v1.y = (float)((double)acc[mi][nj][3] * s + (double)b1);
            *reinterpret_cast<float2*>(g_grad + (size_t)row0 * DD + col) = v0;
            *reinterpret_cast<float2*>(g_grad + (size_t)(row0 + 8) * DD + col) = v1;
        }
}

// ---------------------------------------------------------------------------
// Sampler: per-row Gumbel-max chain, pruned logf, prefetched unif + MH accept.
// ---------------------------------------------------------------------------
#define NT 256
#define PER (DD / NT)

__global__ void __launch_bounds__(NT, 1)
sampler(const float* __restrict__ x, const float* __restrict__ Wm,
        const float* __restrict__ bv, const float* __restrict__ unif,
        const float* __restrict__ u_accept, const int* __restrict__ radius,
        float* __restrict__ out)
{
    __shared__ float lx[DD];
    __shared__ float ly[DD];
    __shared__ signed char ss[DD];
    __shared__ signed char s0[DD];
    __shared__ float rval[8];
    __shared__ int   ridx[8];
    __shared__ double rdbl[NT];
    __shared__ int         fidx[TT];
    __shared__ signed char fsb[TT];
    __shared__ int   cidx[TT];
    __shared__ float cfac[TT];
    __shared__ int   nchg;
    __shared__ float sh_L;
    __shared__ double sh_sx, sh_sy, sh_sf, sh_sb;
    __shared__ int   sh_acc;

    const int r   = blockIdx.x;
    const int tid = threadIdx.x;
    const int rad = radius[r];

    // ---- init: lx, signs, score_x, Lmax ----
    double part = 0.0;
    float lmax = 0.f;
#pragma unroll
    for (int i = 0; i < PER; i++) {
        int j = i * NT + tid;
        float l = 0.5f * g_grad[(size_t)r * DD + j];
        lx[j] = l;
        lmax = fmaxf(lmax, fabsf(l));
        float xv = x[(size_t)r * DD + j];
        signed char sgn = (xv > 0.5f) ? (signed char)(-1) : (signed char)1;
        ss[j] = sgn; s0[j] = sgn;
        if (sgn < 0) part += (double)(l + 0.5f * bv[j]);
    }
#pragma unroll
    for (int off = 16; off > 0; off >>= 1)
        lmax = fmaxf(lmax, __shfl_down_sync(0xffffffffu, lmax, off));
    if ((tid & 31) == 0) rval[tid >> 5] = lmax;
    rdbl[tid] = part; __syncthreads();
    if (tid == 0) {
        float m = rval[0];
        for (int w = 1; w < 8; w++) m = fmaxf(m, rval[w]);
        sh_L = m;
    }
    for (int off = NT / 2; off > 0; off >>= 1) {
        if (tid < off) rdbl[tid] += rdbl[tid + off];
        __syncthreads();
    }
    if (tid == 0) sh_sx = rdbl[0];
    __syncthreads();
    const float Lmax = sh_L;

    // ---- sequential chain with unif prefetch ----
    float4 U0, U1, U2, U3;
    if (rad > 0) {
        const float4* up = reinterpret_cast<const float4*>(unif + (size_t)r * DD);
        U0 = up[tid]; U1 = up[256 + tid]; U2 = up[512 + tid]; U3 = up[768 + tid];
    }
    for (int t = 0; t < rad; t++) {
        float uv[16];
        uv[0] = U0.x; uv[1] = U0.y; uv[2] = U0.z; uv[3] = U0.w;
        uv[4] = U1.x; uv[5] = U1.y; uv[6] = U1.z; uv[7] = U1.w;
        uv[8] = U2.x; uv[9] = U2.y; uv[10] = U2.z; uv[11] = U2.w;
        uv[12] = U3.x; uv[13] = U3.y; uv[14] = U3.z; uv[15] = U3.w;
        float um = -1.f; int im = 0;
#pragma unroll
        for (int i = 0; i < 16; i++) {
            int j = (i >> 2) * 1024 + tid * 4 + (i & 3);
            if (uv[i] > um) { um = uv[i]; im = j; }
        }
        // prefetch next step's unif (hidden under the reductions below)
        if (t + 1 < rad) {
            const float4* un = reinterpret_cast<const float4*>(
                unif + ((size_t)(t + 1) * BB + r) * DD);
            U0 = un[tid]; U1 = un[256 + tid]; U2 = un[512 + tid]; U3 = un[768 + tid];
        }
        // block argmax of u
#pragma unroll
        for (int off = 16; off > 0; off >>= 1) {
            float v2 = __shfl_down_sync(0xffffffffu, um, off);
            int i2 = __shfl_down_sync(0xffffffffu, im, off);
            if (v2 > um || (v2 == um && i2 < im)) { um = v2; im = i2; }
        }
        if ((tid & 31) == 0) { rval[tid >> 5] = um; ridx[tid >> 5] = im; }
        __syncthreads();
        if (tid < 8) {
            float v = rval[tid]; int i = ridx[tid];
#pragma unroll
            for (int off = 4; off > 0; off >>= 1) {
                float v2 = __shfl_down_sync(0xffu, v, off);
                int i2 = __shfl_down_sync(0xffu, i, off);
                if (v2 > v || (v2 == v && i2 < i)) { v = v2; i = i2; }
            }
            if (tid == 0) { rval[0] = v; ridx[0] = i; }
        }
        __syncthreads();
        const float umax = rval[0];
        const int imax = ridx[0];
        const float slm = (float)ss[imax] * lx[imax];
        const float gm = -logf(-logf(umax));
        const float thr_g = gm + slm - Lmax - 0.05f;
        const float uth = expf(-expf(-thr_g));

        // pruned pass: logf only for candidates
        float bvv = -3.4e38f; int bi = 0;
#pragma unroll
        for (int i = 0; i < 16; i++) {
            if (uv[i] >= uth) {
                int j = (i >> 2) * 1024 + tid * 4 + (i & 3);
                float g = -logf(-logf(uv[i]));
                float v = (float)ss[j] * lx[j] + g;
                if (v > bvv) { bvv = v; bi = j; }
            }
        }
#pragma unroll
        for (int off = 16; off > 0; off >>= 1) {
            float v2 = __shfl_down_sync(0xffffffffu, bvv, off);
            int i2 = __shfl_down_sync(0xffffffffu, bi, off);
            if (v2 > bvv || (v2 == bvv && i2 < bi)) { bvv = v2; bi = i2; }
        }
        if ((tid & 31) == 0) { rval[tid >> 5] = bvv; ridx[tid >> 5] = bi; }
        __syncthreads();
        if (tid < 8) {
            float v = rval[tid]; int i = ridx[tid];
#pragma unroll
            for (int off = 4; off > 0; off >>= 1) {
                float v2 = __shfl_down_sync(0xffu, v, off);
                int i2 = __shfl_down_sync(0xffu, i, off);
                if (v2 > v || (v2 == v && i2 < i)) { v = v2; i = i2; }
            }
            if (tid == 0) { fidx[t] = i; fsb[t] = ss[i]; ss[i] = (signed char)(-ss[i]); }
        }
        __syncthreads();
    }

    // ---- net-changed coordinates ----
    if (tid == 0) {
        int n = 0;
        for (int t = 0; t < rad; t++) {
            int i = fidx[t];
            int found = -1;
            for (int k = 0; k < n; k++) if (cidx[k] == i) { found = k; break; }
            if (found >= 0) { cidx[found] = cidx[n - 1]; n--; }
            else cidx[n++] = i;
        }
        nchg = n;
        for (int k = 0; k < n; k++) cfac[k] = -0.5f * (float)ss[cidx[k]];
    }
    __syncthreads();

    // ---- ly = lx + sum cfac_k * W[i_k] (W symmetric) ----
#pragma unroll
    for (int i = 0; i < PER; i++) {
        int j = i * NT + tid;
        ly[j] = lx[j];
    }
    int nc = nchg;
    for (int k = 0; k < nc; k++) {
        const float* wr = Wm + (size_t)cidx[k] * DD;
        float f = cfac[k];
#pragma unroll
        for (int i = 0; i < PER; i++) {
            int j = i * NT + tid;
            ly[j] = fmaf(f, wr[j], ly[j]);
        }
    }

    // ---- score_y + base lse sums ----
    double psy = 0.0, psf = 0.0, psb = 0.0;
#pragma unroll
    for (int i = 0; i < PER; i++) {
        int j = i * NT + tid;
        float lyj = ly[j], lxj = lx[j];
        if (ss[j] < 0) psy += (double)(lyj + 0.5f * bv[j]);
        psf += (double)expf((float)s0[j] * lxj);
        psb += (double)expf((float)ss[j] * lyj);
    }
    rdbl[tid] = psy; __syncthreads();
    for (int off = NT / 2; off > 0; off >>= 1) { if (tid < off) rdbl[tid] += rdbl[tid + off]; __syncthreads(); }
    if (tid == 0) sh_sy = rdbl[0];
    __syncthreads();
    rdbl[tid] = psf; __syncthreads();
    for (int off = NT / 2; off > 0; off >>= 1) { if (tid < off) rdbl[tid] += rdbl[tid + off]; __syncthreads(); }
    if (tid == 0) sh_sf = rdbl[0];
    __syncthreads();
    rdbl[tid] = psb; __syncthreads();
    for (int off = NT / 2; off > 0; off >>= 1) { if (tid < off) rdbl[tid] += rdbl[tid + off]; __syncthreads(); }
    if (tid == 0) sh_sb = rdbl[0];
    __syncthreads();

    // ---- serial accept math (incremental lse walks) ----
    if (tid == 0) {
        double S = sh_sf, lf = 0.0;
        for (int t = 0; t < rad; t++) {
            int i = fidx[t]; float sb = (float)fsb[t]; float l = lx[i];
            lf += (double)(sb * l) - log(S);
            S += exp((double)(-sb * l)) - exp((double)(sb * l));
        }
        lf += sh_sx;

        double Sb = sh_sb, lb = 0.0;
        for (int t = rad - 1; t >= 0; t--) {
            int i = fidx[t]; float sb = (float)fsb[t]; float l = ly[i];
            lb += (double)(-sb * l) - log(Sb);
            Sb += exp((double)(sb * l)) - exp((double)(-sb * l));
        }
        lb += sh_sy;

        float ratio = expf((float)(lb - lf));
        sh_acc = (ratio >= u_accept[r]) ? 1 : 0;
    }
    __syncthreads();

    int acc = sh_acc;
#pragma unroll
    for (int i = 0; i < PER; i++) {
        int j = i * NT + tid;
        float yv = (ss[j] < 0) ? 1.f : 0.f;
        float xv = (s0[j] < 0) ? 1.f : 0.f;
        out[(size_t)r * DD + j] = acc ? yv : xv;
    }
}

// ---------------------------------------------------------------------------
extern "C" void kernel_launch(void* const* d_in, const int* in_sizes, int n_in,
                              void* d_out, int out_size)
{
    (void)in_sizes; (void)n_in; (void)out_size;
    const float* x    = (const float*)d_in[0];
    const float* Wm   = (const float*)d_in[1];
    const float* bv   = (const float*)d_in[2];
    const float* unif = (const float*)d_in[3];
    const float* ua   = (const float*)d_in[4];
    const int*   rad  = (const int*)d_in[5];
    float* out = (float*)d_out;

    static int attr_done = 0;
    if (!attr_done) {
        cudaFuncSetAttribute(gemm_i8, cudaFuncAttributeMaxDynamicSharedMemorySize, GSMEM);
        attr_done = 1;
    }

    conv_w<<<8192, 256>>>(Wm);
    conv_a<<<512, 256>>>(x);
    gemm_i8<<<dim3(64, 2), 256, GSMEM>>>(bv);
    sampler<<<BB, NT>>>(x, Wm, bv, unif, ua, rad, out);
}